// round 8
// baseline (speedup 1.0000x reference)
#include <cuda_runtime.h>
#include <cuda_fp16.h>
#include <cstdint>
#include <cstddef>

// ---------------------------------------------------------------------------
// FeedForwardQuantum on base sm_100 target (no tcgen05 on this build):
//   out[32768,1024] = relu(cos(x[:, :10]) @ W1^T + b1) @ W2^T + b2
// R8 (= R7 resubmit; container infra failed before execution): FUSED kernel.
//   Evidence: GEMM is HMMA-throughput-walled (~512 MAC/cyc/SM; R5 2x-warps
//   neutral, R6 fp16-accum slower). Recover the serial prep_h (~18us) by
//   computing the A-tile (h) inside the GEMM from a smem cos-table, at
//   pipeline distance 2, hidden under the tensor wall.
//   fp32-accum MMA (R4 body). Expected rel_err 2.86e-4.
// ---------------------------------------------------------------------------

#define NTOK 32768
#define EDIM 1024
#define FDIM 1024
#define NQD  10

static __device__ __align__(1024) __half g_w[(size_t)EDIM * FDIM]; // 2 MB

// ------------------------------- helpers -----------------------------------
__device__ __forceinline__ uint32_t smem_u32(const void* p) {
    return (uint32_t)__cvta_generic_to_shared(p);
}
__device__ __forceinline__ void cp_async16(uint32_t dst, const void* src) {
    asm volatile("cp.async.cg.shared.global [%0], [%1], 16;\n" :: "r"(dst), "l"(src));
}
__device__ __forceinline__ void cp_commit() {
    asm volatile("cp.async.commit_group;\n");
}
template <int N>
__device__ __forceinline__ void cp_wait() {
    asm volatile("cp.async.wait_group %0;\n" :: "n"(N));
}
__device__ __forceinline__ void ldsm_x4(uint32_t& r0, uint32_t& r1, uint32_t& r2,
                                        uint32_t& r3, uint32_t addr) {
    asm volatile("ldmatrix.sync.aligned.m8n8.x4.shared.b16 {%0,%1,%2,%3}, [%4];"
                 : "=r"(r0), "=r"(r1), "=r"(r2), "=r"(r3) : "r"(addr));
}
__device__ __forceinline__ void mma16816(float* c, const uint32_t* a, const uint32_t* b) {
    asm volatile(
        "mma.sync.aligned.m16n8k16.row.col.f32.f16.f16.f32 "
        "{%0,%1,%2,%3}, {%4,%5,%6,%7}, {%8,%9}, {%0,%1,%2,%3};"
        : "+f"(c[0]), "+f"(c[1]), "+f"(c[2]), "+f"(c[3])
        : "r"(a[0]), "r"(a[1]), "r"(a[2]), "r"(a[3]), "r"(b[0]), "r"(b[1]));
}
__device__ __forceinline__ uint32_t pack_h2(__half a, __half b) {
    __half2 t = __halves2half2(a, b);
    return *reinterpret_cast<uint32_t*>(&t);
}
__device__ __forceinline__ void sts32(uint32_t addr, uint32_t v) {
    asm volatile("st.shared.b32 [%0], %1;" :: "r"(addr), "r"(v) : "memory");
}

// ---------------------------------------------------------------------------
// K0: W2 [1024,1024] fp32 -> fp16
// ---------------------------------------------------------------------------
__global__ __launch_bounds__(256) void prep_w2_kernel(const float* __restrict__ W2) {
    size_t i = ((size_t)blockIdx.x * 256 + threadIdx.x) * 4;
    float4 v = *reinterpret_cast<const float4*>(W2 + i);
    uint2 hv;
    hv.x = pack_h2(__float2half(v.x), __float2half(v.y));
    hv.y = pack_h2(__float2half(v.z), __float2half(v.w));
    *reinterpret_cast<uint2*>(&g_w[i]) = hv;
}

// ---------------------------------------------------------------------------
// K1 (fused): GEMM with in-kernel A-tile generation.
//   out[m,e] = sum_f relu(cos(x[m,:10])@W1^T+b1)[f] * W2[e,f] + b2[e]
//   CTA tile 128(M) x 256(N), K-chunk 64, 4-stage B cp.async pipeline,
//   A computed into smem stages at distance 2.  8 warps, warp tile 64x64.
//   SW128 swizzle; rows 128B = 64 fp16.
// ---------------------------------------------------------------------------
#define MT 128
#define NT 256
#define KC 64
#define NCHUNK (FDIM / KC) // 16
#define STAGES 4
#define OFF_Bs   16384
#define STAGE_BYTES 49152
#define OFF_CZ (STAGES * STAGE_BYTES)             // 196,608
#define GEMM_SMEM (OFF_CZ + 128 * NQD * 4)        // 201,728 B

__global__ __launch_bounds__(256, 1) void gemm2_kernel(float* __restrict__ out,
                                                       const float* __restrict__ x,
                                                       const float* __restrict__ W1,
                                                       const float* __restrict__ b1,
                                                       const float* __restrict__ b2) {
    extern __shared__ __align__(1024) char smem[];
    const uint32_t sb = smem_u32(smem);
    const int tid = threadIdx.x;
    const int wid = tid >> 5;
    const int lane = tid & 31;
    const int m0 = blockIdx.y * MT;
    const int n0t = blockIdx.x * NT;

    const int warpM = (wid & 1) * 64;
    const int warpN = (wid >> 1) * 64;

    float* cz = reinterpret_cast<float*>(smem + OFF_CZ); // [128][NQD]

    // ---- B cp.async geometry: thread -> (row r+32i, 16B-chunk c16) ----
    const int r = tid >> 3;   // 0..31
    const int c16 = tid & 7;  // 0..7
    const uint32_t dswz = (uint32_t)(r * 128) + (((uint32_t)(c16 * 16)) ^ ((uint32_t)(r & 7) << 4));
    const size_t gB = (size_t)(n0t + r) * FDIM + (size_t)(c16 * 8);

    auto load_B = [&](int stage, int c) {
        const uint32_t st = sb + stage * STAGE_BYTES;
        const size_t ko = (size_t)c * KC;
#pragma unroll
        for (int i = 0; i < 8; i++) { // B: 256 rows
            cp_async16(st + OFF_Bs + dswz + i * 4096, g_w + gB + ko + (size_t)i * 32 * FDIM);
        }
        cp_commit();
    };

    // ---- fused h-compute: thread -> feature pair (lane*2) x 16 tokens ----
    // h[row][k] for k = chunk*64 .. +63 written into stage A region, swizzled.
    auto compute_h = [&](int stage, int c) {
        const uint32_t stA = sb + stage * STAGE_BYTES;
        const int f = c * KC + lane * 2;
        // W1 rows f, f+1 (10 floats each, 8B-aligned) + b1
        float w0[NQD], w1[NQD];
        const float2* p0 = reinterpret_cast<const float2*>(W1 + (size_t)f * NQD);
        const float2* p1 = reinterpret_cast<const float2*>(W1 + (size_t)(f + 1) * NQD);
#pragma unroll
        for (int i = 0; i < 5; i++) {
            float2 a = __ldg(p0 + i); w0[2 * i] = a.x; w0[2 * i + 1] = a.y;
            float2 b = __ldg(p1 + i); w1[2 * i] = b.x; w1[2 * i + 1] = b.y;
        }
        const float bb0 = __ldg(b1 + f), bb1 = __ldg(b1 + f + 1);
        const int row0 = wid * 16;
#pragma unroll
        for (int tk = 0; tk < 16; tk++) {
            const int row = row0 + tk;
            const float2* czr = reinterpret_cast<const float2*>(cz + row * NQD);
            float a0 = bb0, a1 = bb1;
#pragma unroll
            for (int q = 0; q < 5; q++) {
                float2 z2 = czr[q];
                a0 = fmaf(z2.x, w0[2 * q], a0);
                a1 = fmaf(z2.x, w1[2 * q], a1);
                a0 = fmaf(z2.y, w0[2 * q + 1], a0);
                a1 = fmaf(z2.y, w1[2 * q + 1], a1);
            }
            a0 = fmaxf(a0, 0.0f);
            a1 = fmaxf(a1, 0.0f);
            const uint32_t hp = pack_h2(__float2half(a0), __float2half(a1));
            const uint32_t off = ((uint32_t)(row * 128 + lane * 4)) ^ ((uint32_t)(row & 7) << 4);
            sts32(stA + off, hp);
        }
    };

    // ---- ldmatrix geometry ----
    const int r_lane = lane & 7;
    const int grp = lane >> 3;
    const uint32_t xr = (uint32_t)(r_lane << 4);
    const int aRow = warpM + (grp & 1) * 8 + r_lane;
    const uint32_t aColSel = (uint32_t)((grp >> 1) * 16);
    const int bRow = warpN + (grp >> 1) * 8 + r_lane;
    const uint32_t bColSel = (uint32_t)((grp & 1) * 16);

    float acc[4][8][4];
#pragma unroll
    for (int i = 0; i < 4; i++)
#pragma unroll
        for (int j = 0; j < 8; j++)
#pragma unroll
            for (int k = 0; k < 4; k++) acc[i][j][k] = 0.0f;

    // ---- prologue ----
    load_B(0, 0);
    load_B(1, 1);
    load_B(2, 2);

    // cos table: 128 threads, one token each (x row first 10 floats)
    if (tid < 128) {
        const float* xp = x + (size_t)(m0 + tid) * EDIM;
        float4 a = *reinterpret_cast<const float4*>(xp);
        float4 b = *reinterpret_cast<const float4*>(xp + 4);
        float2 d = *reinterpret_cast<const float2*>(xp + 8);
        float* czr = cz + tid * NQD;
        czr[0] = cosf(a.x); czr[1] = cosf(a.y); czr[2] = cosf(a.z); czr[3] = cosf(a.w);
        czr[4] = cosf(b.x); czr[5] = cosf(b.y); czr[6] = cosf(b.z); czr[7] = cosf(b.w);
        czr[8] = cosf(d.x); czr[9] = cosf(d.y);
    }
    __syncthreads(); // cz visible
    compute_h(0, 0);
    compute_h(1, 1);

    // ---- main loop: one barrier per chunk ----
    for (int c = 0; c < NCHUNK; ++c) {
        if (c + 2 < NCHUNK) {
            cp_wait<2>();
        } else if (c + 1 < NCHUNK) {
            cp_wait<1>();
        } else {
            cp_wait<0>();
        }
        // barrier: (a) B(c) visible from all loaders, (b) h(c) STS visible,
        //          (c) all warps done with stage c-2 (safe to refill c+2/c+3)
        __syncthreads();
        if (c + 3 < NCHUNK) load_B((c + 3) % STAGES, c + 3);
        if (c + 2 < NCHUNK) compute_h((c + 2) % STAGES, c + 2);

        const uint32_t st = sb + (c % STAGES) * STAGE_BYTES;
#pragma unroll
        for (int ks = 0; ks < 4; ks++) {
            const uint32_t colA = ((uint32_t)(ks * 32) + aColSel) ^ xr;
            const uint32_t colB = ((uint32_t)(ks * 32) + bColSel) ^ xr;
            uint32_t ah[4][4], bf[8][2];
#pragma unroll
            for (int mt = 0; mt < 4; mt++) {
                const uint32_t ra = st + (uint32_t)((aRow + mt * 16) * 128) + colA;
                ldsm_x4(ah[mt][0], ah[mt][1], ah[mt][2], ah[mt][3], ra);
            }
#pragma unroll
            for (int np = 0; np < 4; np++) {
                const uint32_t rb = st + OFF_Bs + (uint32_t)((bRow + np * 16) * 128) + colB;
                uint32_t q0, q1, q2, q3;
                ldsm_x4(q0, q1, q2, q3, rb);
                bf[np * 2][0] = q0; bf[np * 2][1] = q1;
                bf[np * 2 + 1][0] = q2; bf[np * 2 + 1][1] = q3;
            }
#pragma unroll
            for (int mt = 0; mt < 4; mt++)
#pragma unroll
                for (int nt = 0; nt < 8; nt++) {
                    mma16816(acc[mt][nt], ah[mt], bf[nt]);
                }
        }
    }

    // ---- epilogue: direct stores with bias ----
    const int cr = lane >> 2;          // 0..7
    const int cc = (lane & 3) * 2;     // 0,2,4,6
#pragma unroll
    for (int nt = 0; nt < 8; nt++) {
        const int col = n0t + warpN + nt * 8 + cc;
        const float bx = b2[col], by = b2[col + 1];
#pragma unroll
        for (int mt = 0; mt < 4; mt++) {
            const int row0 = m0 + warpM + mt * 16 + cr;
            float2 v0 = make_float2(acc[mt][nt][0] + bx, acc[mt][nt][1] + by);
            float2 v1 = make_float2(acc[mt][nt][2] + bx, acc[mt][nt][3] + by);
            *reinterpret_cast<float2*>(out + (size_t)row0 * EDIM + col) = v0;
            *reinterpret_cast<float2*>(out + (size_t)(row0 + 8) * EDIM + col) = v1;
        }
    }
}

// ---------------------------------------------------------------------------
// kernel_launch
// inputs: x[33554432], rz_theta[10](unused), W1[10240], b1[1024],
//         W2[1048576], b2[1024]; out fp32 [33554432]
// ---------------------------------------------------------------------------
extern "C" void kernel_launch(void* const* d_in, const int* in_sizes, int n_in,
                              void* d_out, int out_size) {
    (void)in_sizes; (void)n_in; (void)out_size;
    const float* x  = (const float*)d_in[0];
    const float* W1 = (const float*)d_in[2];
    const float* b1 = (const float*)d_in[3];
    const float* W2 = (const float*)d_in[4];
    const float* b2 = (const float*)d_in[5];
    float* out = (float*)d_out;

    cudaFuncSetAttribute(gemm2_kernel, cudaFuncAttributeMaxDynamicSharedMemorySize, GEMM_SMEM);

    prep_w2_kernel<<<1024, 256>>>(W2);
    gemm2_kernel<<<dim3(EDIM / NT, NTOK / MT), 256, GEMM_SMEM>>>(out, x, W1, b1, b2);
}